// round 3
// baseline (speedup 1.0000x reference)
#include <cuda_runtime.h>
#include <math.h>

// ============================================================================
// HFGptOssTopKRouter: logits = X @ W^T + bias; top-4 + softmax.
//   X: [T=16384, H=2880] f32   W: [E=128, H=2880] f32   bias: [E] f32
// Output layout (f32, flatten order of reference tuple):
//   [0, T*4)        router_top_value
//   [T*4, T*8)      router_indices (stored as float)
//   [T*8, T*8+T*E)  router_logits
//
// Numerical strategy: two-level accumulation (fresh fp32 accumulator per
// K-tile of 16, tile sums added into global accumulator) cuts accumulation
// error ~4x vs sequential fp32, minimizing top-4 index flips vs reference.
// ============================================================================

#define BM 128      // token tile
#define BN 128      // expert tile (== E)
#define TK 16       // k tile
#define PAD 4       // smem row padding

__global__ __launch_bounds__(256, 1)
void router_gemm(const float* __restrict__ X,
                 const float* __restrict__ W,
                 const float* __restrict__ bias,
                 float* __restrict__ logits,
                 int T, int H, int E)
{
    __shared__ float As[2][TK][BM + PAD];
    __shared__ float Bs[2][TK][BN + PAD];

    const int tid = threadIdx.x;
    const int m0  = blockIdx.x * BM;
    const int nTiles = H / TK;           // 180

    // loader mapping: 512 float4-chunks per operand tile, 2 per thread
    const int c0 = tid, c1 = tid + 256;
    const int ar0 = c0 >> 2, ak0 = (c0 & 3) << 2;
    const int ar1 = c1 >> 2, ak1 = (c1 & 3) << 2;

    // compute mapping: 16x16 thread grid, 8x8 microtile
    const int tx = tid & 15;
    const int ty = tid >> 4;

    float sum[8][8];
#pragma unroll
    for (int i = 0; i < 8; i++)
#pragma unroll
        for (int j = 0; j < 8; j++) sum[i][j] = 0.0f;

    const float* Xa0 = X + (size_t)(m0 + ar0) * H + ak0;
    const float* Xa1 = X + (size_t)(m0 + ar1) * H + ak1;
    const float* Wb0 = W + (size_t)ar0 * H + ak0;
    const float* Wb1 = W + (size_t)ar1 * H + ak1;

    // --- load tile 0 ---
    float4 pa0 = *(const float4*)(Xa0);
    float4 pa1 = *(const float4*)(Xa1);
    float4 pb0 = *(const float4*)(Wb0);
    float4 pb1 = *(const float4*)(Wb1);

    {
        As[0][ak0+0][ar0] = pa0.x; As[0][ak0+1][ar0] = pa0.y;
        As[0][ak0+2][ar0] = pa0.z; As[0][ak0+3][ar0] = pa0.w;
        As[0][ak1+0][ar1] = pa1.x; As[0][ak1+1][ar1] = pa1.y;
        As[0][ak1+2][ar1] = pa1.z; As[0][ak1+3][ar1] = pa1.w;
        Bs[0][ak0+0][ar0] = pb0.x; Bs[0][ak0+1][ar0] = pb0.y;
        Bs[0][ak0+2][ar0] = pb0.z; Bs[0][ak0+3][ar0] = pb0.w;
        Bs[0][ak1+0][ar1] = pb1.x; Bs[0][ak1+1][ar1] = pb1.y;
        Bs[0][ak1+2][ar1] = pb1.z; Bs[0][ak1+3][ar1] = pb1.w;
    }
    __syncthreads();

    for (int kt = 0; kt < nTiles; kt++) {
        const int buf = kt & 1;
        const bool more = (kt + 1) < nTiles;

        if (more) {
            const int ko = (kt + 1) * TK;
            pa0 = *(const float4*)(Xa0 + ko);
            pa1 = *(const float4*)(Xa1 + ko);
            pb0 = *(const float4*)(Wb0 + ko);
            pb1 = *(const float4*)(Wb1 + ko);
        }

        // fresh tile accumulator (keeps partial sums tiny -> tiny rounding err)
        float t[8][8];
#pragma unroll
        for (int i = 0; i < 8; i++)
#pragma unroll
            for (int j = 0; j < 8; j++) t[i][j] = 0.0f;

#pragma unroll
        for (int k = 0; k < TK; k++) {
            float4 a0 = *(const float4*)&As[buf][k][ty * 8];
            float4 a1 = *(const float4*)&As[buf][k][ty * 8 + 4];
            float4 b0 = *(const float4*)&Bs[buf][k][tx * 8];
            float4 b1 = *(const float4*)&Bs[buf][k][tx * 8 + 4];
            float a[8] = {a0.x, a0.y, a0.z, a0.w, a1.x, a1.y, a1.z, a1.w};
            float b[8] = {b0.x, b0.y, b0.z, b0.w, b1.x, b1.y, b1.z, b1.w};
#pragma unroll
            for (int i = 0; i < 8; i++)
#pragma unroll
                for (int j = 0; j < 8; j++)
                    t[i][j] = fmaf(a[i], b[j], t[i][j]);
        }

        // combine tile sum into global sum (two-level accumulation)
#pragma unroll
        for (int i = 0; i < 8; i++)
#pragma unroll
            for (int j = 0; j < 8; j++) sum[i][j] += t[i][j];

        if (more) {
            const int nb = buf ^ 1;
            As[nb][ak0+0][ar0] = pa0.x; As[nb][ak0+1][ar0] = pa0.y;
            As[nb][ak0+2][ar0] = pa0.z; As[nb][ak0+3][ar0] = pa0.w;
            As[nb][ak1+0][ar1] = pa1.x; As[nb][ak1+1][ar1] = pa1.y;
            As[nb][ak1+2][ar1] = pa1.z; As[nb][ak1+3][ar1] = pa1.w;
            Bs[nb][ak0+0][ar0] = pb0.x; Bs[nb][ak0+1][ar0] = pb0.y;
            Bs[nb][ak0+2][ar0] = pb0.z; Bs[nb][ak0+3][ar0] = pb0.w;
            Bs[nb][ak1+0][ar1] = pb1.x; Bs[nb][ak1+1][ar1] = pb1.y;
            Bs[nb][ak1+2][ar1] = pb1.z; Bs[nb][ak1+3][ar1] = pb1.w;
        }
        __syncthreads();
    }

    // --- epilogue: add bias, write logits ---
    const int col = tx * 8;
    float bv[8];
#pragma unroll
    for (int j = 0; j < 8; j++) bv[j] = bias[col + j];

#pragma unroll
    for (int i = 0; i < 8; i++) {
        const int row = m0 + ty * 8 + i;
        float4 o0, o1;
        o0.x = sum[i][0] + bv[0]; o0.y = sum[i][1] + bv[1];
        o0.z = sum[i][2] + bv[2]; o0.w = sum[i][3] + bv[3];
        o1.x = sum[i][4] + bv[4]; o1.y = sum[i][5] + bv[5];
        o1.z = sum[i][6] + bv[6]; o1.w = sum[i][7] + bv[7];
        float* p = logits + (size_t)row * E + col;
        *(float4*)(p)     = o0;
        *(float4*)(p + 4) = o1;
    }
}

// ----------------------------------------------------------------------------
// Top-4 + softmax, one warp per token (E=128, 4 logits per lane).
// Tie-break matches jax.lax.top_k: larger value first, lower index on equal.
// ----------------------------------------------------------------------------
__global__ void topk_softmax(const float* __restrict__ logits,
                             float* __restrict__ topv,
                             float* __restrict__ topi,
                             int T, int E)
{
    const int warp = (blockIdx.x * blockDim.x + threadIdx.x) >> 5;
    if (warp >= T) return;
    const int lane = threadIdx.x & 31;

    const float* row = logits + (size_t)warp * E;
    float v[4]; int idx[4];
#pragma unroll
    for (int j = 0; j < 4; j++) {
        idx[j] = lane + 32 * j;
        v[j]   = row[idx[j]];
    }

    float outv[4]; int outi[4];
#pragma unroll
    for (int k = 0; k < 4; k++) {
        // local best among unconsumed (local idx ascending -> strict > keeps lowest idx)
        float bv = v[0]; int bi = idx[0];
#pragma unroll
        for (int j = 1; j < 4; j++)
            if (v[j] > bv) { bv = v[j]; bi = idx[j]; }
        // warp argmax with lowest-index tie-break
#pragma unroll
        for (int off = 16; off > 0; off >>= 1) {
            float ov = __shfl_xor_sync(0xFFFFFFFFu, bv, off);
            int   oi = __shfl_xor_sync(0xFFFFFFFFu, bi, off);
            if (ov > bv || (ov == bv && oi < bi)) { bv = ov; bi = oi; }
        }
        outv[k] = bv; outi[k] = bi;
#pragma unroll
        for (int j = 0; j < 4; j++)
            if (idx[j] == bi) v[j] = -INFINITY;
    }

    if (lane == 0) {
        const float m = outv[0];
        float e[4], s = 0.0f;
#pragma unroll
        for (int k = 0; k < 4; k++) { e[k] = expf(outv[k] - m); s += e[k]; }
        const float inv = 1.0f / s;
        float* pv = topv + (size_t)warp * 4;
        float* pi = topi + (size_t)warp * 4;
#pragma unroll
        for (int k = 0; k < 4; k++) {
            pv[k] = e[k] * inv;
            pi[k] = (float)outi[k];
        }
    }
}

// ----------------------------------------------------------------------------
extern "C" void kernel_launch(void* const* d_in, const int* in_sizes, int n_in,
                              void* d_out, int out_size)
{
    const float* X    = (const float*)d_in[0];   // hidden_states [T,H]
    const float* W    = (const float*)d_in[1];   // weight [E,H]
    const float* bias = (const float*)d_in[2];   // bias [E]

    const int E = in_sizes[2];            // 128
    const int H = in_sizes[1] / E;        // 2880
    const int T = in_sizes[0] / H;        // 16384

    float* out    = (float*)d_out;
    float* topv   = out;                         // [T,4]
    float* topi   = out + (size_t)T * 4;         // [T,4] (indices as float)
    float* logits = out + (size_t)T * 8;         // [T,E]

    router_gemm<<<T / BM, 256>>>(X, W, bias, logits, T, H, E);

    const int warpsPerBlock = 8;
    const int blocks = (T + warpsPerBlock - 1) / warpsPerBlock;
    topk_softmax<<<blocks, warpsPerBlock * 32>>>(logits, topv, topi, T, E);
}

// round 5
// speedup vs baseline: 1.2083x; 1.2083x over previous
#include <cuda_runtime.h>
#include <cuda_bf16.h>
#include <math.h>
#include <stdint.h>

// ============================================================================
// HFGptOssTopKRouter: logits = X @ W^T + bias ; top-4 + softmax.
//   X: [T=16384, H=2880] f32   W: [E=128, H=2880] f32   bias: [E] f32
// Output (f32): [topv T*4 | indices-as-f32 T*4 | logits T*E]
//
// Speed: bf16 2-way-split mma.sync GEMM (3 products -> fp32 acc), err ~1e-5.
// Index exactness: tokens whose top-5 adjacent gaps < DELTA get exact fp32
// recompute (two-level accumulation) in a tiny refine kernel.
// ============================================================================

#define E_FIXED 128
#define H_MAX   2880
#define DELTA   5e-4f

__device__ __nv_bfloat16 g_wsplit[2][E_FIXED * H_MAX];  // W bf16 split planes
__device__ int g_refine_count;
__device__ int g_refine_list[16384];

// ---------------- helpers ----------------
__device__ __forceinline__ uint32_t smem_u32(const void* p) {
    uint32_t a;
    asm("{ .reg .u64 t; cvta.to.shared.u64 t, %1; cvt.u32.u64 %0, t; }" : "=r"(a) : "l"(p));
    return a;
}

__device__ __forceinline__ void ldsm4(uint32_t& r0, uint32_t& r1, uint32_t& r2,
                                      uint32_t& r3, uint32_t addr) {
    asm volatile("ldmatrix.sync.aligned.m8n8.x4.shared.b16 {%0,%1,%2,%3}, [%4];"
                 : "=r"(r0), "=r"(r1), "=r"(r2), "=r"(r3) : "r"(addr));
}

__device__ __forceinline__ void mma16816(float c[4], const uint32_t a[4],
                                         const uint32_t b[2]) {
    asm volatile(
        "mma.sync.aligned.m16n8k16.row.col.f32.bf16.bf16.f32 "
        "{%0,%1,%2,%3}, {%4,%5,%6,%7}, {%8,%9}, {%0,%1,%2,%3};"
        : "+f"(c[0]), "+f"(c[1]), "+f"(c[2]), "+f"(c[3])
        : "r"(a[0]), "r"(a[1]), "r"(a[2]), "r"(a[3]), "r"(b[0]), "r"(b[1]));
}

// 2-way bf16 split of a float pair -> packed bf16x2 (lo plane, hi-residual plane)
__device__ __forceinline__ void split2(float a, float b, uint32_t& m0, uint32_t& m1) {
    __nv_bfloat162 p0 = __floats2bfloat162_rn(a, b);
    float2 q = __bfloat1622float2(p0);
    __nv_bfloat162 p1 = __floats2bfloat162_rn(a - q.x, b - q.y);
    m0 = *reinterpret_cast<uint32_t*>(&p0);
    m1 = *reinterpret_cast<uint32_t*>(&p1);
}

// ---------------- prep: split W into 2 bf16 planes ----------------
__global__ void wsplit_kernel(const float* __restrict__ W, int n) {
    int i = blockIdx.x * blockDim.x + threadIdx.x;
    if (i >= n) return;
    float x = W[i];
    __nv_bfloat16 b0 = __float2bfloat16_rn(x);
    float r1 = x - __bfloat162float(b0);
    g_wsplit[0][i] = b0;
    g_wsplit[1][i] = __float2bfloat16_rn(r1);
}

__global__ void zero_kernel() { g_refine_count = 0; }

// ---------------- main GEMM: mma.sync bf16 split ----------------
// Tile: BM=128 tokens, BN=128 experts, BK=32, 256 threads (8 warps, 4x2 grid).
// SMEM: A planes [buf*2+p] 10240B each (row stride 80B = odd*16B, conflict-free
// ldmatrix), B same. Total dynamic smem = 81920 B.
#define BK        32
#define ROWB      80u            // bytes per smem row (40 bf16)
#define PLANE     10240u         // 128 * 80
#define OFF_A     0u
#define OFF_B     40960u
#define SMEM_SZ   81920u

__global__ __launch_bounds__(256, 1)
void router_gemm_mma(const float* __restrict__ X,
                     const float* __restrict__ bias,
                     float* __restrict__ logits,
                     int H)
{
    extern __shared__ __align__(128) char smem[];
    const uint32_t sb = smem_u32(smem);
    const int tid  = threadIdx.x;
    const int wid  = tid >> 5;
    const int lane = tid & 31;
    const int m0   = blockIdx.x * 128;
    const int nStages = H / BK;                 // 90

    // producer mapping: 2 threads per row, 16 k each
    const int prow  = tid >> 1;
    const int phalf = tid & 1;
    const float* xptr = X + (size_t)(m0 + prow) * H + phalf * 16;
    const __nv_bfloat16* w0ptr = g_wsplit[0] + (size_t)prow * H + phalf * 16;
    const __nv_bfloat16* w1ptr = g_wsplit[1] + (size_t)prow * H + phalf * 16;
    const uint32_t stsOff = (uint32_t)prow * ROWB + (uint32_t)phalf * 32u;

    // consumer mapping
    const int warp_m = wid & 3;                 // 0..3 -> 32 rows each
    const int warp_n = wid >> 2;                // 0..1 -> 64 cols each
    const int lane15 = lane & 15;
    const uint32_t aRowB = (uint32_t)(warp_m * 32 + lane15) * ROWB;
    const uint32_t aKd   = (uint32_t)((lane >> 4) << 3) * 2u;
    const int q = lane >> 3;
    const uint32_t bRowB = (uint32_t)(warp_n * 64 + ((q >> 1) << 3) + (lane & 7)) * ROWB;
    const uint32_t bKd   = (uint32_t)((q & 1) << 3) * 2u;

    float C[2][8][4];
#pragma unroll
    for (int mt = 0; mt < 2; mt++)
#pragma unroll
        for (int nt = 0; nt < 8; nt++)
#pragma unroll
            for (int r = 0; r < 4; r++) C[mt][nt][r] = 0.0f;

    float4 xv[4];
    uint4  wv[2][2];

    // prefetch + store stage 0
    {
        const float4* xq = (const float4*)(xptr);
#pragma unroll
        for (int i = 0; i < 4; i++) xv[i] = xq[i];
        wv[0][0] = ((const uint4*)(w0ptr))[0]; wv[0][1] = ((const uint4*)(w0ptr))[1];
        wv[1][0] = ((const uint4*)(w1ptr))[0]; wv[1][1] = ((const uint4*)(w1ptr))[1];
    }
    {
        uint32_t p0[8], p1[8];
        const float* xf = (const float*)xv;
#pragma unroll
        for (int i = 0; i < 8; i++) split2(xf[2*i], xf[2*i+1], p0[i], p1[i]);
        *(uint4*)(smem + OFF_A + 0*PLANE + stsOff)      = make_uint4(p0[0],p0[1],p0[2],p0[3]);
        *(uint4*)(smem + OFF_A + 0*PLANE + stsOff + 16) = make_uint4(p0[4],p0[5],p0[6],p0[7]);
        *(uint4*)(smem + OFF_A + 1*PLANE + stsOff)      = make_uint4(p1[0],p1[1],p1[2],p1[3]);
        *(uint4*)(smem + OFF_A + 1*PLANE + stsOff + 16) = make_uint4(p1[4],p1[5],p1[6],p1[7]);
        *(uint4*)(smem + OFF_B + 0*PLANE + stsOff)      = wv[0][0];
        *(uint4*)(smem + OFF_B + 0*PLANE + stsOff + 16) = wv[0][1];
        *(uint4*)(smem + OFF_B + 1*PLANE + stsOff)      = wv[1][0];
        *(uint4*)(smem + OFF_B + 1*PLANE + stsOff + 16) = wv[1][1];
    }
    __syncthreads();

    for (int s = 0; s < nStages; s++) {
        const int buf = s & 1;
        const bool more = (s + 1) < nStages;

        if (more) {
            const int ko = (s + 1) * BK;
            const float4* xq = (const float4*)(xptr + ko);
#pragma unroll
            for (int i = 0; i < 4; i++) xv[i] = xq[i];
            wv[0][0] = ((const uint4*)(w0ptr + ko))[0]; wv[0][1] = ((const uint4*)(w0ptr + ko))[1];
            wv[1][0] = ((const uint4*)(w1ptr + ko))[0]; wv[1][1] = ((const uint4*)(w1ptr + ko))[1];
        }

        // ---- compute on buf ----
        const uint32_t aBase0 = sb + OFF_A + (uint32_t)(buf * 2 + 0) * PLANE;
        const uint32_t aBase1 = sb + OFF_A + (uint32_t)(buf * 2 + 1) * PLANE;
        const uint32_t bBase0 = sb + OFF_B + (uint32_t)(buf * 2 + 0) * PLANE;
        const uint32_t bBase1 = sb + OFF_B + (uint32_t)(buf * 2 + 1) * PLANE;
#pragma unroll
        for (int kk = 0; kk < BK; kk += 16) {
            const uint32_t kb = (uint32_t)kk * 2u;
            uint32_t a[2][2][4];
#pragma unroll
            for (int mt = 0; mt < 2; mt++) {
                ldsm4(a[0][mt][0], a[0][mt][1], a[0][mt][2], a[0][mt][3],
                      aBase0 + aRowB + (uint32_t)(mt * 16) * ROWB + kb + aKd);
                ldsm4(a[1][mt][0], a[1][mt][1], a[1][mt][2], a[1][mt][3],
                      aBase1 + aRowB + (uint32_t)(mt * 16) * ROWB + kb + aKd);
            }
            uint32_t b[2][8][2];
#pragma unroll
            for (int np = 0; np < 4; np++) {
                ldsm4(b[0][2*np][0], b[0][2*np][1], b[0][2*np+1][0], b[0][2*np+1][1],
                      bBase0 + bRowB + (uint32_t)(np * 16) * ROWB + kb + bKd);
                ldsm4(b[1][2*np][0], b[1][2*np][1], b[1][2*np+1][0], b[1][2*np+1][1],
                      bBase1 + bRowB + (uint32_t)(np * 16) * ROWB + kb + bKd);
            }
#pragma unroll
            for (int mt = 0; mt < 2; mt++)
#pragma unroll
                for (int nt = 0; nt < 8; nt++) {
                    mma16816(C[mt][nt], a[0][mt], b[0][nt]);   // x0*w0
                    mma16816(C[mt][nt], a[0][mt], b[1][nt]);   // x0*w1
                    mma16816(C[mt][nt], a[1][mt], b[0][nt]);   // x1*w0
                }
        }

        // ---- store stage s+1 into buf^1 ----
        if (more) {
            const uint32_t nb = (uint32_t)((buf ^ 1) * 2);
            uint32_t p0[8], p1[8];
            const float* xf = (const float*)xv;
#pragma unroll
            for (int i = 0; i < 8; i++) split2(xf[2*i], xf[2*i+1], p0[i], p1[i]);
            *(uint4*)(smem + OFF_A + (nb+0)*PLANE + stsOff)      = make_uint4(p0[0],p0[1],p0[2],p0[3]);
            *(uint4*)(smem + OFF_A + (nb+0)*PLANE + stsOff + 16) = make_uint4(p0[4],p0[5],p0[6],p0[7]);
            *(uint4*)(smem + OFF_A + (nb+1)*PLANE + stsOff)      = make_uint4(p1[0],p1[1],p1[2],p1[3]);
            *(uint4*)(smem + OFF_A + (nb+1)*PLANE + stsOff + 16) = make_uint4(p1[4],p1[5],p1[6],p1[7]);
            *(uint4*)(smem + OFF_B + (nb+0)*PLANE + stsOff)      = wv[0][0];
            *(uint4*)(smem + OFF_B + (nb+0)*PLANE + stsOff + 16) = wv[0][1];
            *(uint4*)(smem + OFF_B + (nb+1)*PLANE + stsOff)      = wv[1][0];
            *(uint4*)(smem + OFF_B + (nb+1)*PLANE + stsOff + 16) = wv[1][1];
        }
        __syncthreads();
    }

    // ---- epilogue: bias add, write logits ----
#pragma unroll
    for (int mt = 0; mt < 2; mt++) {
        const int r = m0 + warp_m * 32 + mt * 16 + (lane >> 2);
#pragma unroll
        for (int nt = 0; nt < 8; nt++) {
            const int cidx = warp_n * 64 + nt * 8 + (lane & 3) * 2;
            const float b0v = __ldg(bias + cidx);
            const float b1v = __ldg(bias + cidx + 1);
            float2 v0 = make_float2(C[mt][nt][0] + b0v, C[mt][nt][1] + b1v);
            float2 v1 = make_float2(C[mt][nt][2] + b0v, C[mt][nt][3] + b1v);
            *(float2*)(logits + (size_t)r * 128 + cidx)       = v0;
            *(float2*)(logits + (size_t)(r + 8) * 128 + cidx) = v1;
        }
    }
}

// ---------------- top-4 + softmax with uncertainty detection ----------------
__global__ void topk_softmax(const float* __restrict__ logits,
                             float* __restrict__ topv,
                             float* __restrict__ topi,
                             int T, int E)
{
    const int warp = (blockIdx.x * blockDim.x + threadIdx.x) >> 5;
    if (warp >= T) return;
    const int lane = threadIdx.x & 31;

    const float* row = logits + (size_t)warp * E;
    float v[4]; int idx[4];
#pragma unroll
    for (int j = 0; j < 4; j++) { idx[j] = lane + 32 * j; v[j] = row[idx[j]]; }

    float outv[5]; int outi[5];
#pragma unroll
    for (int k = 0; k < 5; k++) {
        float bv = v[0]; int bi = idx[0];
#pragma unroll
        for (int j = 1; j < 4; j++)
            if (v[j] > bv) { bv = v[j]; bi = idx[j]; }
#pragma unroll
        for (int off = 16; off > 0; off >>= 1) {
            float ov = __shfl_xor_sync(0xFFFFFFFFu, bv, off);
            int   oi = __shfl_xor_sync(0xFFFFFFFFu, bi, off);
            if (ov > bv || (ov == bv && oi < bi)) { bv = ov; bi = oi; }
        }
        outv[k] = bv; outi[k] = bi;
#pragma unroll
        for (int j = 0; j < 4; j++)
            if (idx[j] == bi) v[j] = -INFINITY;
    }

    if (lane == 0) {
        // certainty check: all adjacent gaps among ranks 1..5 must exceed DELTA
        float minGap = outv[0] - outv[1];
#pragma unroll
        for (int k = 1; k < 4; k++) {
            float g = outv[k] - outv[k + 1];
            if (g < minGap) minGap = g;
        }
        if (minGap < DELTA) {
            int slot = atomicAdd(&g_refine_count, 1);
            g_refine_list[slot] = warp;
        }
        const float m = outv[0];
        float e[4], s = 0.0f;
#pragma unroll
        for (int k = 0; k < 4; k++) { e[k] = expf(outv[k] - m); s += e[k]; }
        const float inv = 1.0f / s;
        float* pv = topv + (size_t)warp * 4;
        float* pi = topi + (size_t)warp * 4;
#pragma unroll
        for (int k = 0; k < 4; k++) { pv[k] = e[k] * inv; pi[k] = (float)outi[k]; }
    }
}

// ---------------- refine: exact fp32 logits for uncertain tokens ----------------
__global__ void refine_kernel(const float* __restrict__ X,
                              const float* __restrict__ W,
                              const float* __restrict__ bias,
                              float* __restrict__ topv,
                              float* __restrict__ topi,
                              int H)
{
    __shared__ float vals[128];
    const int nref = g_refine_count;
    const int e = threadIdx.x;              // expert, 0..127

    for (int b = blockIdx.x; b < nref; b += gridDim.x) {
        const int token = g_refine_list[b];
        const float* xp = X + (size_t)token * H;
        const float* wp = W + (size_t)e * H;
        float sum = 0.0f;
        for (int kt = 0; kt < H; kt += 16) {        // two-level accumulation
            float t = 0.0f;
#pragma unroll
            for (int k = 0; k < 16; k += 4) {
                float4 x4 = *(const float4*)(xp + kt + k);
                float4 w4 = *(const float4*)(wp + kt + k);
                t = fmaf(x4.x, w4.x, t);
                t = fmaf(x4.y, w4.y, t);
                t = fmaf(x4.z, w4.z, t);
                t = fmaf(x4.w, w4.w, t);
            }
            sum += t;
        }
        vals[e] = sum + bias[e];
        __syncthreads();

        if (e < 32) {
            const int lane = e;
            float v[4]; int idx[4];
#pragma unroll
            for (int j = 0; j < 4; j++) { idx[j] = lane + 32 * j; v[j] = vals[idx[j]]; }
            float outv[4]; int outi[4];
#pragma unroll
            for (int k = 0; k < 4; k++) {
                float bv = v[0]; int bi = idx[0];
#pragma unroll
                for (int j = 1; j < 4; j++)
                    if (v[j] > bv) { bv = v[j]; bi = idx[j]; }
#pragma unroll
                for (int off = 16; off > 0; off >>= 1) {
                    float ov = __shfl_xor_sync(0xFFFFFFFFu, bv, off);
                    int   oi = __shfl_xor_sync(0xFFFFFFFFu, bi, off);
                    if (ov > bv || (ov == bv && oi < bi)) { bv = ov; bi = oi; }
                }
                outv[k] = bv; outi[k] = bi;
#pragma unroll
                for (int j = 0; j < 4; j++)
                    if (idx[j] == bi) v[j] = -INFINITY;
            }
            if (lane == 0) {
                const float m = outv[0];
                float ee[4], s = 0.0f;
#pragma unroll
                for (int k = 0; k < 4; k++) { ee[k] = expf(outv[k] - m); s += ee[k]; }
                const float inv = 1.0f / s;
                float* pv = topv + (size_t)token * 4;
                float* pi = topi + (size_t)token * 4;
#pragma unroll
                for (int k = 0; k < 4; k++) { pv[k] = ee[k] * inv; pi[k] = (float)outi[k]; }
            }
        }
        __syncthreads();
    }
}

// ----------------------------------------------------------------------------
extern "C" void kernel_launch(void* const* d_in, const int* in_sizes, int n_in,
                              void* d_out, int out_size)
{
    const float* X    = (const float*)d_in[0];
    const float* W    = (const float*)d_in[1];
    const float* bias = (const float*)d_in[2];

    const int E = in_sizes[2];            // 128
    const int H = in_sizes[1] / E;        // 2880
    const int T = in_sizes[0] / H;        // 16384

    float* out    = (float*)d_out;
    float* topv   = out;
    float* topi   = out + (size_t)T * 4;
    float* logits = out + (size_t)T * 8;

    {
        const int n = E * H;
        wsplit_kernel<<<(n + 255) / 256, 256>>>(W, n);
    }
    zero_kernel<<<1, 1>>>();

    cudaFuncSetAttribute(router_gemm_mma,
                         cudaFuncAttributeMaxDynamicSharedMemorySize, SMEM_SZ);
    router_gemm_mma<<<T / 128, 256, SMEM_SZ>>>(X, bias, logits, H);

    const int warpsPerBlock = 8;
    topk_softmax<<<(T + warpsPerBlock - 1) / warpsPerBlock, warpsPerBlock * 32>>>(
        logits, topv, topi, T, E);

    refine_kernel<<<256, 128>>>(X, W, bias, topv, topi, H);
}